// round 1
// baseline (speedup 1.0000x reference)
#include <cuda_runtime.h>

#define NMAX   100000
#define EMAX   1600000
#define HD     64

// ---------------- scratch (device globals; no allocation) ----------------
__device__ __align__(16) float g_h[NMAX * HD];   // layer activations
__device__ __align__(16) float g_t[NMAX * HD];   // transformed (h @ W)
__device__ float g_deg[NMAX];
__device__ float g_dinv[NMAX];
__device__ int   g_cnt[NMAX];
__device__ int   g_cur[NMAX];
__device__ int   g_rowptr[NMAX + 1];
__device__ int   g_src[EMAX];
__device__ float g_nrm[EMAX];

// ---------------- graph preprocessing ----------------
__global__ void k_init(int n) {
    int i = blockIdx.x * blockDim.x + threadIdx.x;
    if (i < n) { g_deg[i] = 1.0f; g_cnt[i] = 0; g_cur[i] = 0; }
}

__global__ void k_degcnt(const int* __restrict__ ei, const float* __restrict__ ew, int e) {
    int i = blockIdx.x * blockDim.x + threadIdx.x;
    if (i >= e) return;
    int d = ei[e + i];                 // dst
    atomicAdd(&g_deg[d], ew[i]);
    atomicAdd(&g_cnt[d], 1);
}

__global__ void k_dinv(int n) {
    int i = blockIdx.x * blockDim.x + threadIdx.x;
    if (i < n) {
        float dg = g_deg[i];
        g_dinv[i] = (dg > 0.0f) ? rsqrtf(dg) : 0.0f;
    }
}

// single-block exclusive scan of g_cnt -> g_rowptr  (n <= 1024*chunk)
__global__ void k_scan(int n) {
    __shared__ int sums[1024];
    int t = threadIdx.x;
    int chunk = (n + 1023) >> 10;
    int beg = t * chunk;
    int end = beg + chunk; if (end > n) end = n;
    int s = 0;
    for (int i = beg; i < end; i++) s += g_cnt[i];
    sums[t] = s;
    __syncthreads();
    // Hillis-Steele inclusive scan
    for (int off = 1; off < 1024; off <<= 1) {
        int v = 0;
        if (t >= off) v = sums[t - off];
        __syncthreads();
        sums[t] += v;
        __syncthreads();
    }
    int run = sums[t] - s;             // exclusive prefix for this chunk
    for (int i = beg; i < end; i++) {
        g_rowptr[i] = run;
        run += g_cnt[i];
    }
    if (beg < n && end == n) g_rowptr[n] = run;
}

__global__ void k_fill(const int* __restrict__ ei, const float* __restrict__ ew, int e) {
    int i = blockIdx.x * blockDim.x + threadIdx.x;
    if (i >= e) return;
    int s = ei[i];                     // src
    int d = ei[e + i];                 // dst
    float nr = g_dinv[s] * ew[i] * g_dinv[d];
    int p = g_rowptr[d] + atomicAdd(&g_cur[d], 1);
    g_src[p] = s;
    g_nrm[p] = nr;
}

// ---------------- fp32 GEMM: out[n x 64] = A[n x KDIM] @ W[KDIM x 64] ----------------
template <int KDIM>
__global__ void k_gemm64(const float* __restrict__ A, const float* __restrict__ W,
                         float* __restrict__ out, int n) {
    __shared__ float As[64][36];       // padded: stride 36 floats (144B, 16B aligned)
    __shared__ float Ws[32][64];
    int tid = threadIdx.x;             // 256 threads
    int tx = tid & 15;                 // 16 col-groups of 4
    int ty = tid >> 4;                 // 16 row-groups of 4
    int row0 = blockIdx.x * 64;

    float acc[4][4];
#pragma unroll
    for (int i = 0; i < 4; i++)
#pragma unroll
        for (int j = 0; j < 4; j++) acc[i][j] = 0.0f;

    for (int kk = 0; kk < KDIM; kk += 32) {
        // load A tile 64x32 (2048 floats) with float4
#pragma unroll
        for (int it = 0; it < 2; it++) {
            int j = (tid + it * 256) * 4;     // 0..2044
            int r = j >> 5;                    // /32
            int c = j & 31;
            float4 v = make_float4(0.f, 0.f, 0.f, 0.f);
            int grow = row0 + r;
            if (grow < n)
                v = *(const float4*)&A[(size_t)grow * KDIM + kk + c];
            *(float4*)&As[r][c] = v;
        }
        // load W tile 32x64 (2048 floats)
#pragma unroll
        for (int it = 0; it < 2; it++) {
            int j = (tid + it * 256) * 4;
            int kr = j >> 6;                   // /64
            int c = j & 63;
            *(float4*)&Ws[kr][c] = *(const float4*)&W[(size_t)(kk + kr) * 64 + c];
        }
        __syncthreads();
#pragma unroll
        for (int k = 0; k < 32; k++) {
            float a0 = As[ty * 4 + 0][k];
            float a1 = As[ty * 4 + 1][k];
            float a2 = As[ty * 4 + 2][k];
            float a3 = As[ty * 4 + 3][k];
            float4 b = *(float4*)&Ws[k][tx * 4];
            acc[0][0] += a0 * b.x; acc[0][1] += a0 * b.y; acc[0][2] += a0 * b.z; acc[0][3] += a0 * b.w;
            acc[1][0] += a1 * b.x; acc[1][1] += a1 * b.y; acc[1][2] += a1 * b.z; acc[1][3] += a1 * b.w;
            acc[2][0] += a2 * b.x; acc[2][1] += a2 * b.y; acc[2][2] += a2 * b.z; acc[2][3] += a2 * b.w;
            acc[3][0] += a3 * b.x; acc[3][1] += a3 * b.y; acc[3][2] += a3 * b.z; acc[3][3] += a3 * b.w;
        }
        __syncthreads();
    }
#pragma unroll
    for (int i = 0; i < 4; i++) {
        int grow = row0 + ty * 4 + i;
        if (grow < n)
            *(float4*)&out[(size_t)grow * 64 + tx * 4] =
                make_float4(acc[i][0], acc[i][1], acc[i][2], acc[i][3]);
    }
}

// ---------------- aggregation: out = relu( D^-1/2 (A+I) D^-1/2 t + b ) ----------------
__global__ void k_agg(const float* __restrict__ t, const float* __restrict__ bias,
                      float* __restrict__ out, int n) {
    int node = blockIdx.x * 4 + (threadIdx.x >> 6);
    int f = threadIdx.x & 63;
    if (node >= n) return;
    float di = g_dinv[node];
    float acc = t[node * 64 + f] * di * di;        // self-loop (w=1)
    int p = g_rowptr[node];
    int p1 = g_rowptr[node + 1];
    int pm = p + ((p1 - p) & ~3);
    for (; p < pm; p += 4) {
        int s0 = g_src[p + 0], s1 = g_src[p + 1], s2 = g_src[p + 2], s3 = g_src[p + 3];
        float n0 = g_nrm[p + 0], n1 = g_nrm[p + 1], n2 = g_nrm[p + 2], n3 = g_nrm[p + 3];
        float v0 = t[s0 * 64 + f];
        float v1 = t[s1 * 64 + f];
        float v2 = t[s2 * 64 + f];
        float v3 = t[s3 * 64 + f];
        acc += v0 * n0;
        acc += v1 * n1;
        acc += v2 * n2;
        acc += v3 * n3;
    }
    for (; p < p1; p++)
        acc += t[g_src[p] * 64 + f] * g_nrm[p];
    out[node * 64 + f] = fmaxf(acc + bias[f], 0.0f);
}

// ---------------- doc head: relu(h[doc] @ Wp + bp) @ Wc + bc ----------------
__global__ void k_dochead(const float* __restrict__ h, const int* __restrict__ doc,
                          const float* __restrict__ Wp, const float* __restrict__ bp,
                          const float* __restrict__ Wc, const float* __restrict__ bc,
                          float* __restrict__ out, int ndoc, int C) {
    __shared__ float sWp[64 * 64];
    __shared__ float sWc[64 * 32];
    __shared__ float sh[4][64];
    __shared__ float sp[4][64];
    int tid = threadIdx.x;             // 256
    for (int i = tid; i < 64 * 64; i += 256) sWp[i] = Wp[i];
    for (int i = tid; i < 64 * C; i += 256) sWc[i] = Wc[i];

    int dl = tid >> 6;
    int f = tid & 63;
    int d = blockIdx.x * 4 + dl;
    if (d < ndoc) {
        int node = doc[d];
        sh[dl][f] = h[node * 64 + f];
    }
    __syncthreads();
    if (d < ndoc) {
        float acc = bp[f];
#pragma unroll
        for (int k = 0; k < 64; k++)
            acc += sh[dl][k] * sWp[k * 64 + f];
        sp[dl][f] = fmaxf(acc, 0.0f);
    }
    __syncthreads();
    if (d < ndoc && f < C) {
        float acc = bc[f];
#pragma unroll
        for (int k = 0; k < 64; k++)
            acc += sp[dl][k] * sWc[k * C + f];
        out[d * C + f] = acc;
    }
}

// ---------------- launch ----------------
extern "C" void kernel_launch(void* const* d_in, const int* in_sizes, int n_in,
                              void* d_out, int out_size) {
    const float* x    = (const float*)d_in[0];
    const float* ew   = (const float*)d_in[1];
    const float* W1   = (const float*)d_in[2];
    const float* b1   = (const float*)d_in[3];
    const float* W2   = (const float*)d_in[4];
    const float* b2   = (const float*)d_in[5];
    const float* W3   = (const float*)d_in[6];
    const float* b3   = (const float*)d_in[7];
    const float* Wp   = (const float*)d_in[8];
    const float* bp   = (const float*)d_in[9];
    const float* Wc   = (const float*)d_in[10];
    const float* bc   = (const float*)d_in[11];
    const int*   ei   = (const int*)d_in[12];
    const int*   doc  = (const int*)d_in[13];
    float* out = (float*)d_out;

    int H    = in_sizes[3];               // 64
    int DIN  = in_sizes[2] / H;           // 256
    int n    = in_sizes[0] / DIN;         // 100000
    int e    = in_sizes[1];               // 1600000
    int C    = in_sizes[11];              // 20
    int ndoc = in_sizes[13];              // 10000

    float* th; float* tt;
    cudaGetSymbolAddress((void**)&th, g_h);
    cudaGetSymbolAddress((void**)&tt, g_t);

    int nb_n = (n + 255) / 256;
    int nb_e = (e + 255) / 256;
    int nb_g = (n + 63) / 64;
    int nb_a = (n + 3) / 4;

    // graph preprocessing
    k_init<<<nb_n, 256>>>(n);
    k_degcnt<<<nb_e, 256>>>(ei, ew, e);
    k_dinv<<<nb_n, 256>>>(n);
    k_scan<<<1, 1024>>>(n);
    k_fill<<<nb_e, 256>>>(ei, ew, e);

    // layer 1
    k_gemm64<256><<<nb_g, 256>>>(x, W1, tt, n);
    k_agg<<<nb_a, 256>>>(tt, b1, th, n);
    // layer 2
    k_gemm64<64><<<nb_g, 256>>>(th, W2, tt, n);
    k_agg<<<nb_a, 256>>>(tt, b2, th, n);
    // layer 3
    k_gemm64<64><<<nb_g, 256>>>(th, W3, tt, n);
    k_agg<<<nb_a, 256>>>(tt, b3, th, n);

    // doc head
    k_dochead<<<(ndoc + 3) / 4, 256>>>(th, doc, Wp, bp, Wc, bc, out, ndoc, C);
}

// round 2
// speedup vs baseline: 1.2471x; 1.2471x over previous
#include <cuda_runtime.h>

#define NMAX   100000
#define EMAX   1600000
#define HD     64
#define SCAN_B 1024                      // elems per scan block

// ---------------- scratch (device globals; no allocation) ----------------
__device__ __align__(16) float g_h[NMAX * HD];   // layer activations
__device__ __align__(16) float g_t[NMAX * HD];   // transformed (h @ W)
__device__ float g_deg[NMAX];
__device__ float g_dinv[NMAX];
__device__ int   g_cnt[NMAX];
__device__ int   g_cur[NMAX];
__device__ int   g_rowptr[NMAX + 1];
__device__ int   g_src[EMAX];
__device__ float g_nrm[EMAX];
__device__ int   g_bsum[1024];
__device__ int   g_boff[1024];

// ---------------- graph preprocessing ----------------
__global__ void k_init(int n) {
    int i = blockIdx.x * blockDim.x + threadIdx.x;
    if (i < n) { g_deg[i] = 1.0f; g_cnt[i] = 0; g_cur[i] = 0; }
}

__global__ void k_degcnt(const int* __restrict__ ei, const float* __restrict__ ew, int e) {
    int i = blockIdx.x * blockDim.x + threadIdx.x;
    if (i >= e) return;
    int d = ei[e + i];                 // dst
    atomicAdd(&g_deg[d], ew[i]);
    atomicAdd(&g_cnt[d], 1);
}

// phase 1: per-block reduction of g_cnt; also computes dinv (deg is final here)
__global__ void k_scan1(int n) {
    __shared__ int sh[SCAN_B];
    int t = threadIdx.x;
    int i = blockIdx.x * SCAN_B + t;
    int v = (i < n) ? g_cnt[i] : 0;
    if (i < n) {
        float dg = g_deg[i];
        g_dinv[i] = (dg > 0.0f) ? rsqrtf(dg) : 0.0f;
    }
    sh[t] = v;
    __syncthreads();
#pragma unroll
    for (int off = SCAN_B / 2; off > 0; off >>= 1) {
        if (t < off) sh[t] += sh[t + off];
        __syncthreads();
    }
    if (t == 0) g_bsum[blockIdx.x] = sh[0];
}

// phase 2: exclusive scan of block sums (nb <= 1024), single block
__global__ void k_scan2(int nb) {
    __shared__ int sh[1024];
    int t = threadIdx.x;
    int v = (t < nb) ? g_bsum[t] : 0;
    sh[t] = v;
    __syncthreads();
#pragma unroll
    for (int off = 1; off < 1024; off <<= 1) {
        int u = (t >= off) ? sh[t - off] : 0;
        __syncthreads();
        sh[t] += u;
        __syncthreads();
    }
    if (t < nb) g_boff[t] = sh[t] - v;   // exclusive prefix
}

// phase 3: block-local exclusive scan + block offset -> rowptr
__global__ void k_scan3(int n) {
    __shared__ int sh[SCAN_B];
    int t = threadIdx.x;
    int i = blockIdx.x * SCAN_B + t;
    int v = (i < n) ? g_cnt[i] : 0;
    sh[t] = v;
    __syncthreads();
#pragma unroll
    for (int off = 1; off < SCAN_B; off <<= 1) {
        int u = (t >= off) ? sh[t - off] : 0;
        __syncthreads();
        sh[t] += u;
        __syncthreads();
    }
    int excl = sh[t] - v + g_boff[blockIdx.x];
    if (i < n) {
        g_rowptr[i] = excl;
        if (i == n - 1) g_rowptr[n] = excl + v;
    }
}

__global__ void k_fill(const int* __restrict__ ei, const float* __restrict__ ew, int e) {
    int i = blockIdx.x * blockDim.x + threadIdx.x;
    if (i >= e) return;
    int s = ei[i];                     // src
    int d = ei[e + i];                 // dst
    float nr = g_dinv[s] * ew[i] * g_dinv[d];
    int p = g_rowptr[d] + atomicAdd(&g_cur[d], 1);
    g_src[p] = s;
    g_nrm[p] = nr;
}

// ---------------- fp32 GEMM: out[n x 64] = A[n x KDIM] @ W[KDIM x 64] ----------------
template <int KDIM>
__global__ void k_gemm64(const float* __restrict__ A, const float* __restrict__ W,
                         float* __restrict__ out, int n) {
    __shared__ float As[64][36];       // padded: stride 36 floats
    __shared__ float Ws[32][64];
    int tid = threadIdx.x;             // 256 threads
    int tx = tid & 15;                 // 16 col-groups of 4
    int ty = tid >> 4;                 // 16 row-groups of 4
    int row0 = blockIdx.x * 64;

    float acc[4][4];
#pragma unroll
    for (int i = 0; i < 4; i++)
#pragma unroll
        for (int j = 0; j < 4; j++) acc[i][j] = 0.0f;

    for (int kk = 0; kk < KDIM; kk += 32) {
#pragma unroll
        for (int it = 0; it < 2; it++) {
            int j = (tid + it * 256) * 4;     // 0..2044
            int r = j >> 5;
            int c = j & 31;
            float4 v = make_float4(0.f, 0.f, 0.f, 0.f);
            int grow = row0 + r;
            if (grow < n)
                v = *(const float4*)&A[(size_t)grow * KDIM + kk + c];
            *(float4*)&As[r][c] = v;
        }
#pragma unroll
        for (int it = 0; it < 2; it++) {
            int j = (tid + it * 256) * 4;
            int kr = j >> 6;
            int c = j & 63;
            *(float4*)&Ws[kr][c] = *(const float4*)&W[(size_t)(kk + kr) * 64 + c];
        }
        __syncthreads();
#pragma unroll
        for (int k = 0; k < 32; k++) {
            float a0 = As[ty * 4 + 0][k];
            float a1 = As[ty * 4 + 1][k];
            float a2 = As[ty * 4 + 2][k];
            float a3 = As[ty * 4 + 3][k];
            float4 b = *(float4*)&Ws[k][tx * 4];
            acc[0][0] += a0 * b.x; acc[0][1] += a0 * b.y; acc[0][2] += a0 * b.z; acc[0][3] += a0 * b.w;
            acc[1][0] += a1 * b.x; acc[1][1] += a1 * b.y; acc[1][2] += a1 * b.z; acc[1][3] += a1 * b.w;
            acc[2][0] += a2 * b.x; acc[2][1] += a2 * b.y; acc[2][2] += a2 * b.z; acc[2][3] += a2 * b.w;
            acc[3][0] += a3 * b.x; acc[3][1] += a3 * b.y; acc[3][2] += a3 * b.z; acc[3][3] += a3 * b.w;
        }
        __syncthreads();
    }
#pragma unroll
    for (int i = 0; i < 4; i++) {
        int grow = row0 + ty * 4 + i;
        if (grow < n)
            *(float4*)&out[(size_t)grow * 64 + tx * 4] =
                make_float4(acc[i][0], acc[i][1], acc[i][2], acc[i][3]);
    }
}

// ---------------- aggregation: out = relu( D^-1/2 (A+I) D^-1/2 t + b ) ----------------
__global__ void k_agg(const float* __restrict__ t, const float* __restrict__ bias,
                      float* __restrict__ out, int n) {
    int node = blockIdx.x * 4 + (threadIdx.x >> 6);
    int f = threadIdx.x & 63;
    if (node >= n) return;
    float di = g_dinv[node];
    float acc = t[node * 64 + f] * di * di;        // self-loop (w=1)
    int p = g_rowptr[node];
    int p1 = g_rowptr[node + 1];
    int pm = p + ((p1 - p) & ~3);
    for (; p < pm; p += 4) {
        int s0 = g_src[p + 0], s1 = g_src[p + 1], s2 = g_src[p + 2], s3 = g_src[p + 3];
        float n0 = g_nrm[p + 0], n1 = g_nrm[p + 1], n2 = g_nrm[p + 2], n3 = g_nrm[p + 3];
        float v0 = t[s0 * 64 + f];
        float v1 = t[s1 * 64 + f];
        float v2 = t[s2 * 64 + f];
        float v3 = t[s3 * 64 + f];
        acc += v0 * n0;
        acc += v1 * n1;
        acc += v2 * n2;
        acc += v3 * n3;
    }
    for (; p < p1; p++)
        acc += t[g_src[p] * 64 + f] * g_nrm[p];
    out[node * 64 + f] = fmaxf(acc + bias[f], 0.0f);
}

// ---------------- doc head: relu(h[doc] @ Wp + bp) @ Wc + bc ----------------
__global__ void k_dochead(const float* __restrict__ h, const int* __restrict__ doc,
                          const float* __restrict__ Wp, const float* __restrict__ bp,
                          const float* __restrict__ Wc, const float* __restrict__ bc,
                          float* __restrict__ out, int ndoc, int C) {
    __shared__ float sWp[64 * 64];
    __shared__ float sWc[64 * 32];
    __shared__ float sh[4][64];
    __shared__ float sp[4][64];
    int tid = threadIdx.x;             // 256
    for (int i = tid; i < 64 * 64; i += 256) sWp[i] = Wp[i];
    for (int i = tid; i < 64 * C; i += 256) sWc[i] = Wc[i];

    int dl = tid >> 6;
    int f = tid & 63;
    int d = blockIdx.x * 4 + dl;
    if (d < ndoc) {
        int node = doc[d];
        sh[dl][f] = h[node * 64 + f];
    }
    __syncthreads();
    if (d < ndoc) {
        float acc = bp[f];
#pragma unroll
        for (int k = 0; k < 64; k++)
            acc += sh[dl][k] * sWp[k * 64 + f];
        sp[dl][f] = fmaxf(acc, 0.0f);
    }
    __syncthreads();
    if (d < ndoc && f < C) {
        float acc = bc[f];
#pragma unroll
        for (int k = 0; k < 64; k++)
            acc += sp[dl][k] * sWc[k * C + f];
        out[d * C + f] = acc;
    }
}

// ---------------- launch ----------------
extern "C" void kernel_launch(void* const* d_in, const int* in_sizes, int n_in,
                              void* d_out, int out_size) {
    const float* x    = (const float*)d_in[0];
    const float* ew   = (const float*)d_in[1];
    const float* W1   = (const float*)d_in[2];
    const float* b1   = (const float*)d_in[3];
    const float* W2   = (const float*)d_in[4];
    const float* b2   = (const float*)d_in[5];
    const float* W3   = (const float*)d_in[6];
    const float* b3   = (const float*)d_in[7];
    const float* Wp   = (const float*)d_in[8];
    const float* bp   = (const float*)d_in[9];
    const float* Wc   = (const float*)d_in[10];
    const float* bc   = (const float*)d_in[11];
    const int*   ei   = (const int*)d_in[12];
    const int*   doc  = (const int*)d_in[13];
    float* out = (float*)d_out;

    int H    = in_sizes[3];               // 64
    int DIN  = in_sizes[2] / H;           // 256
    int n    = in_sizes[0] / DIN;         // 100000
    int e    = in_sizes[1];               // 1600000
    int C    = in_sizes[11];              // 20
    int ndoc = in_sizes[13];              // 10000

    float* th; float* tt;
    cudaGetSymbolAddress((void**)&th, g_h);
    cudaGetSymbolAddress((void**)&tt, g_t);

    int nb_n = (n + 255) / 256;
    int nb_e = (e + 255) / 256;
    int nb_g = (n + 63) / 64;
    int nb_a = (n + 3) / 4;
    int nb_s = (n + SCAN_B - 1) / SCAN_B;

    // graph preprocessing
    k_init<<<nb_n, 256>>>(n);
    k_degcnt<<<nb_e, 256>>>(ei, ew, e);
    k_scan1<<<nb_s, SCAN_B>>>(n);          // block sums + dinv
    k_scan2<<<1, 1024>>>(nb_s);            // scan block sums
    k_scan3<<<nb_s, SCAN_B>>>(n);          // rowptr
    k_fill<<<nb_e, 256>>>(ei, ew, e);

    // layer 1
    k_gemm64<256><<<nb_g, 256>>>(x, W1, tt, n);
    k_agg<<<nb_a, 256>>>(tt, b1, th, n);
    // layer 2
    k_gemm64<64><<<nb_g, 256>>>(th, W2, tt, n);
    k_agg<<<nb_a, 256>>>(tt, b2, th, n);
    // layer 3
    k_gemm64<64><<<nb_g, 256>>>(th, W3, tt, n);
    k_agg<<<nb_a, 256>>>(tt, b3, th, n);

    // doc head
    k_dochead<<<(ndoc + 3) / 4, 256>>>(th, doc, Wp, bp, Wc, bc, out, ndoc, C);
}

// round 3
// speedup vs baseline: 1.3177x; 1.0566x over previous
#include <cuda_runtime.h>

#define NMAX   100000
#define EMAX   1600000
#define HD     64
#define SCAN_B 1024                      // elems per scan block

// ---------------- scratch (device globals; no allocation) ----------------
__device__ __align__(16) float g_h[NMAX * HD];   // layer activations
__device__ __align__(16) float g_t[NMAX * HD];   // transformed (h @ W)
__device__ float g_deg[NMAX];
__device__ float g_dinv[NMAX];
__device__ int   g_cnt[NMAX];
__device__ int   g_cur[NMAX];
__device__ int   g_rowptr[NMAX + 1];
__device__ int   g_src[EMAX];
__device__ float g_nrm[EMAX];
__device__ int   g_bsum[1024];
__device__ int   g_boff[1024];

// ---------------- stream/event infra (host objects only; created once) ----
struct OverlapCtx {
    cudaStream_t s2;
    cudaEvent_t evFork, evJoin;
    OverlapCtx() {
        cudaStreamCreateWithFlags(&s2, cudaStreamNonBlocking);
        cudaEventCreateWithFlags(&evFork, cudaEventDisableTiming);
        cudaEventCreateWithFlags(&evJoin, cudaEventDisableTiming);
    }
};
static OverlapCtx g_ctx;

// ---------------- graph preprocessing ----------------
__global__ void k_init(int n) {
    int i = blockIdx.x * blockDim.x + threadIdx.x;
    if (i < n) { g_deg[i] = 1.0f; g_cnt[i] = 0; g_cur[i] = 0; }
}

__global__ void k_degcnt(const int* __restrict__ ei, const float* __restrict__ ew, int e) {
    int i = blockIdx.x * blockDim.x + threadIdx.x;
    if (i >= e) return;
    int d = ei[e + i];                 // dst
    atomicAdd(&g_deg[d], ew[i]);
    atomicAdd(&g_cnt[d], 1);
}

// phase 1: per-block reduction of g_cnt; also computes dinv (deg is final here)
__global__ void k_scan1(int n) {
    __shared__ int sh[SCAN_B];
    int t = threadIdx.x;
    int i = blockIdx.x * SCAN_B + t;
    int v = (i < n) ? g_cnt[i] : 0;
    if (i < n) {
        float dg = g_deg[i];
        g_dinv[i] = (dg > 0.0f) ? rsqrtf(dg) : 0.0f;
    }
    sh[t] = v;
    __syncthreads();
#pragma unroll
    for (int off = SCAN_B / 2; off > 0; off >>= 1) {
        if (t < off) sh[t] += sh[t + off];
        __syncthreads();
    }
    if (t == 0) g_bsum[blockIdx.x] = sh[0];
}

// phase 2: exclusive scan of block sums (nb <= 1024), single block
__global__ void k_scan2(int nb) {
    __shared__ int sh[1024];
    int t = threadIdx.x;
    int v = (t < nb) ? g_bsum[t] : 0;
    sh[t] = v;
    __syncthreads();
#pragma unroll
    for (int off = 1; off < 1024; off <<= 1) {
        int u = (t >= off) ? sh[t - off] : 0;
        __syncthreads();
        sh[t] += u;
        __syncthreads();
    }
    if (t < nb) g_boff[t] = sh[t] - v;   // exclusive prefix
}

// phase 3: block-local exclusive scan + block offset -> rowptr
__global__ void k_scan3(int n) {
    __shared__ int sh[SCAN_B];
    int t = threadIdx.x;
    int i = blockIdx.x * SCAN_B + t;
    int v = (i < n) ? g_cnt[i] : 0;
    sh[t] = v;
    __syncthreads();
#pragma unroll
    for (int off = 1; off < SCAN_B; off <<= 1) {
        int u = (t >= off) ? sh[t - off] : 0;
        __syncthreads();
        sh[t] += u;
        __syncthreads();
    }
    int excl = sh[t] - v + g_boff[blockIdx.x];
    if (i < n) {
        g_rowptr[i] = excl;
        if (i == n - 1) g_rowptr[n] = excl + v;
    }
}

__global__ void k_fill(const int* __restrict__ ei, const float* __restrict__ ew, int e) {
    int i = blockIdx.x * blockDim.x + threadIdx.x;
    if (i >= e) return;
    int s = ei[i];                     // src
    int d = ei[e + i];                 // dst
    float nr = g_dinv[s] * ew[i] * g_dinv[d];
    int p = g_rowptr[d] + atomicAdd(&g_cur[d], 1);
    g_src[p] = s;
    g_nrm[p] = nr;
}

// ---------------- fp32 GEMM: out[n x 64] = A[n x KDIM] @ W[KDIM x 64] ----------------
template <int KDIM>
__global__ void k_gemm64(const float* __restrict__ A, const float* __restrict__ W,
                         float* __restrict__ out, int n) {
    __shared__ float As[64][36];       // padded: stride 36 floats
    __shared__ float Ws[32][64];
    int tid = threadIdx.x;             // 256 threads
    int tx = tid & 15;                 // 16 col-groups of 4
    int ty = tid >> 4;                 // 16 row-groups of 4
    int row0 = blockIdx.x * 64;

    float acc[4][4];
#pragma unroll
    for (int i = 0; i < 4; i++)
#pragma unroll
        for (int j = 0; j < 4; j++) acc[i][j] = 0.0f;

    for (int kk = 0; kk < KDIM; kk += 32) {
#pragma unroll
        for (int it = 0; it < 2; it++) {
            int j = (tid + it * 256) * 4;     // 0..2044
            int r = j >> 5;
            int c = j & 31;
            float4 v = make_float4(0.f, 0.f, 0.f, 0.f);
            int grow = row0 + r;
            if (grow < n)
                v = *(const float4*)&A[(size_t)grow * KDIM + kk + c];
            *(float4*)&As[r][c] = v;
        }
#pragma unroll
        for (int it = 0; it < 2; it++) {
            int j = (tid + it * 256) * 4;
            int kr = j >> 6;
            int c = j & 63;
            *(float4*)&Ws[kr][c] = *(const float4*)&W[(size_t)(kk + kr) * 64 + c];
        }
        __syncthreads();
#pragma unroll
        for (int k = 0; k < 32; k++) {
            float a0 = As[ty * 4 + 0][k];
            float a1 = As[ty * 4 + 1][k];
            float a2 = As[ty * 4 + 2][k];
            float a3 = As[ty * 4 + 3][k];
            float4 b = *(float4*)&Ws[k][tx * 4];
            acc[0][0] += a0 * b.x; acc[0][1] += a0 * b.y; acc[0][2] += a0 * b.z; acc[0][3] += a0 * b.w;
            acc[1][0] += a1 * b.x; acc[1][1] += a1 * b.y; acc[1][2] += a1 * b.z; acc[1][3] += a1 * b.w;
            acc[2][0] += a2 * b.x; acc[2][1] += a2 * b.y; acc[2][2] += a2 * b.z; acc[2][3] += a2 * b.w;
            acc[3][0] += a3 * b.x; acc[3][1] += a3 * b.y; acc[3][2] += a3 * b.z; acc[3][3] += a3 * b.w;
        }
        __syncthreads();
    }
#pragma unroll
    for (int i = 0; i < 4; i++) {
        int grow = row0 + ty * 4 + i;
        if (grow < n)
            *(float4*)&out[(size_t)grow * 64 + tx * 4] =
                make_float4(acc[i][0], acc[i][1], acc[i][2], acc[i][3]);
    }
}

// ---------------- aggregation: out = relu( D^-1/2 (A+I) D^-1/2 t + b ) ----------------
__global__ void k_agg(const float* __restrict__ t, const float* __restrict__ bias,
                      float* __restrict__ out, int n) {
    int node = blockIdx.x * 4 + (threadIdx.x >> 6);
    int f = threadIdx.x & 63;
    if (node >= n) return;
    float di = g_dinv[node];
    float acc = t[node * 64 + f] * di * di;        // self-loop (w=1)
    int p = g_rowptr[node];
    int p1 = g_rowptr[node + 1];
    int pm = p + ((p1 - p) & ~3);
    for (; p < pm; p += 4) {
        int s0 = g_src[p + 0], s1 = g_src[p + 1], s2 = g_src[p + 2], s3 = g_src[p + 3];
        float n0 = g_nrm[p + 0], n1 = g_nrm[p + 1], n2 = g_nrm[p + 2], n3 = g_nrm[p + 3];
        float v0 = t[s0 * 64 + f];
        float v1 = t[s1 * 64 + f];
        float v2 = t[s2 * 64 + f];
        float v3 = t[s3 * 64 + f];
        acc += v0 * n0;
        acc += v1 * n1;
        acc += v2 * n2;
        acc += v3 * n3;
    }
    for (; p < p1; p++)
        acc += t[g_src[p] * 64 + f] * g_nrm[p];
    out[node * 64 + f] = fmaxf(acc + bias[f], 0.0f);
}

// ---------------- doc head: relu(h[doc] @ Wp + bp) @ Wc + bc ----------------
__global__ void k_dochead(const float* __restrict__ h, const int* __restrict__ doc,
                          const float* __restrict__ Wp, const float* __restrict__ bp,
                          const float* __restrict__ Wc, const float* __restrict__ bc,
                          float* __restrict__ out, int ndoc, int C) {
    __shared__ float sWp[64 * 64];
    __shared__ float sWc[64 * 32];
    __shared__ float sh[4][64];
    __shared__ float sp[4][64];
    int tid = threadIdx.x;             // 256
    for (int i = tid; i < 64 * 64; i += 256) sWp[i] = Wp[i];
    for (int i = tid; i < 64 * C; i += 256) sWc[i] = Wc[i];

    int dl = tid >> 6;
    int f = tid & 63;
    int d = blockIdx.x * 4 + dl;
    if (d < ndoc) {
        int node = doc[d];
        sh[dl][f] = h[node * 64 + f];
    }
    __syncthreads();
    if (d < ndoc) {
        float acc = bp[f];
#pragma unroll
        for (int k = 0; k < 64; k++)
            acc += sh[dl][k] * sWp[k * 64 + f];
        sp[dl][f] = fmaxf(acc, 0.0f);
    }
    __syncthreads();
    if (d < ndoc && f < C) {
        float acc = bc[f];
#pragma unroll
        for (int k = 0; k < 64; k++)
            acc += sp[dl][k] * sWc[k * C + f];
        out[d * C + f] = acc;
    }
}

// ---------------- launch ----------------
extern "C" void kernel_launch(void* const* d_in, const int* in_sizes, int n_in,
                              void* d_out, int out_size) {
    const float* x    = (const float*)d_in[0];
    const float* ew   = (const float*)d_in[1];
    const float* W1   = (const float*)d_in[2];
    const float* b1   = (const float*)d_in[3];
    const float* W2   = (const float*)d_in[4];
    const float* b2   = (const float*)d_in[5];
    const float* W3   = (const float*)d_in[6];
    const float* b3   = (const float*)d_in[7];
    const float* Wp   = (const float*)d_in[8];
    const float* bp   = (const float*)d_in[9];
    const float* Wc   = (const float*)d_in[10];
    const float* bc   = (const float*)d_in[11];
    const int*   ei   = (const int*)d_in[12];
    const int*   doc  = (const int*)d_in[13];
    float* out = (float*)d_out;

    int H    = in_sizes[3];               // 64
    int DIN  = in_sizes[2] / H;           // 256
    int n    = in_sizes[0] / DIN;         // 100000
    int e    = in_sizes[1];               // 1600000
    int C    = in_sizes[11];              // 20
    int ndoc = in_sizes[13];              // 10000

    float* th; float* tt;
    cudaGetSymbolAddress((void**)&th, g_h);
    cudaGetSymbolAddress((void**)&tt, g_t);

    int nb_n = (n + 255) / 256;
    int nb_e = (e + 255) / 256;
    int nb_g = (n + 63) / 64;
    int nb_a = (n + 3) / 4;
    int nb_s = (n + SCAN_B - 1) / SCAN_B;

    // ---- fork: GEMM1 (x @ W1) runs on side stream, overlapping preprocessing ----
    cudaEventRecord(g_ctx.evFork, 0);
    cudaStreamWaitEvent(g_ctx.s2, g_ctx.evFork, 0);
    k_gemm64<256><<<nb_g, 256, 0, g_ctx.s2>>>(x, W1, tt, n);
    cudaEventRecord(g_ctx.evJoin, g_ctx.s2);

    // ---- preprocessing on main stream ----
    k_init<<<nb_n, 256>>>(n);
    k_degcnt<<<nb_e, 256>>>(ei, ew, e);
    k_scan1<<<nb_s, SCAN_B>>>(n);          // block sums + dinv
    k_scan2<<<1, 1024>>>(nb_s);            // scan block sums
    k_scan3<<<nb_s, SCAN_B>>>(n);          // rowptr
    k_fill<<<nb_e, 256>>>(ei, ew, e);

    // ---- join: agg1 needs both CSR and GEMM1 output ----
    cudaStreamWaitEvent(0, g_ctx.evJoin, 0);

    k_agg<<<nb_a, 256>>>(tt, b1, th, n);
    // layer 2
    k_gemm64<64><<<nb_g, 256>>>(th, W2, tt, n);
    k_agg<<<nb_a, 256>>>(tt, b2, th, n);
    // layer 3
    k_gemm64<64><<<nb_g, 256>>>(th, W3, tt, n);
    k_agg<<<nb_a, 256>>>(tt, b3, th, n);

    // doc head
    k_dochead<<<(ndoc + 3) / 4, 256>>>(th, doc, Wp, bp, Wc, bc, out, ndoc, C);
}